// round 7
// baseline (speedup 1.0000x reference)
#include <cuda_runtime.h>
#include <cuda_bf16.h>
#include <math.h>

#define B 64
#define T 256
#define F 64
#define H 1024
#define G4H 4096
#define NCTA 128
#define NTHR 256
#define PSTRIDE 66

typedef unsigned long long ull;
typedef unsigned int u32;

// ---------------- scratch globals ----------------
__device__ __align__(256) float g_xg[(size_t)T * G4H * B];   // [T][4096][B]
__device__ __align__(256) float g_actA[(size_t)T * H * B];   // [T][H][B]
__device__ __align__(256) float g_actB[(size_t)T * H * B];   // [T][H][B]
// fragment-packed A images: entry (kc, mt, lane) -> 16B (4 words)
__device__ __align__(256) unsigned char g_hImg[2][64 * 8 * 32 * 16];          // per-step h image
__device__ __align__(256) unsigned char g_xImg[(size_t)T * 64 * 8 * 32 * 16]; // per-t x image
__device__ __align__(256) unsigned g_flags2[NCTA];           // grid-barrier flags (epoch counters)

// ---------------- generic helpers ----------------
__device__ __forceinline__ ull splat2(float x) {
    ull r; asm("mov.b64 %0, {%1, %1};" : "=l"(r) : "f"(x)); return r;
}
__device__ __forceinline__ void fma2(ull& d, ull a, ull b) {
    asm("fma.rn.f32x2 %0, %1, %2, %0;" : "+l"(d) : "l"(a), "l"(b));
}
__device__ __forceinline__ float sigf(float x) { return 1.f / (1.f + __expf(-x)); }

// Flag-array grid barrier: distinct-address arrivals, per-thread polling.
// target is an absolute epoch (base + step + 1); wrap-safe signed compare.
__device__ __forceinline__ void grid_barrier2(unsigned target, int tid, int cb) {
    __threadfence();
    __syncthreads();
    if (tid == 0) *(volatile unsigned*)&g_flags2[cb] = target;
    if (tid < NCTA) {
        while ((int)(*(volatile unsigned*)&g_flags2[tid] - target) < 0) { }
    }
    __threadfence();
    __syncthreads();
}

__device__ __forceinline__ u32 packbf(float a, float b) {
    unsigned short la = __bfloat16_as_ushort(__float2bfloat16_rn(a));
    unsigned short lb = __bfloat16_as_ushort(__float2bfloat16_rn(b));
    return (u32)la | ((u32)lb << 16);
}

__device__ __forceinline__ void mma_bf16(float* d, const uint4& a, u32 b0, u32 b1) {
    asm volatile(
        "mma.sync.aligned.m16n8k16.row.col.f32.bf16.bf16.f32 "
        "{%0,%1,%2,%3},{%4,%5,%6,%7},{%8,%9},{%0,%1,%2,%3};"
        : "+f"(d[0]), "+f"(d[1]), "+f"(d[2]), "+f"(d[3])
        : "r"(a.x), "r"(a.y), "r"(a.z), "r"(a.w), "r"(b0), "r"(b1));
}

__device__ __forceinline__ u32 smem_u32(const void* p) {
    u32 a;
    asm("{ .reg .u64 t; cvta.to.shared.u64 t, %1; cvt.u32.u64 %0, t; }" : "=r"(a) : "l"(p));
    return a;
}

// ---------------- shared HMMA machinery ----------------
// SMEM layout (bytes), common to rec and xg_mma kernels:
#define OFF_WHI 0           // 64KB  W hi fragments
#define OFF_WLO 65536       // 64KB  W lo fragments
#define OFF_A0  131072      // 32KB  A chunk buffer 0
#define OFF_A1  163840      // 32KB  A chunk buffer 1
#define OFF_ZHI 196608      // 128*33*4 = 16896
#define OFF_ZLO 213504      // 64*33*4  = 8448
#define OFF_AUX 221952      // 2KB aux (rec: hsb staging; xg: bias)
#define SMEM_REC 224000
#define KCC 8               // kc per chunk
#define NCHK 8              // chunks per K=1024
#define ABUF_B (KCC * 8 * 32 * 16)   // 32768

// Pack a 32-gate-column weight slice into B-fragment layout, split hi/lo bf16.
__device__ void pack_w(const float* __restrict__ w, char* smem, int cb, int tid) {
    int nt = tid >> 6;            // 0..3
    int l  = (tid >> 1) & 31;
    int word = tid & 1;
    int j = nt * 8 + (l >> 2);    // local col 0..31
    int row = (j >> 3) * H + cb * 8 + (j & 7);
    const float* src = w + (size_t)row * H;
    for (int kc = 0; kc < 64; kc++) {
        int k0 = kc * 16 + (l & 3) * 2 + word * 8;
        float v0 = __ldg(src + k0), v1 = __ldg(src + k0 + 1);
        float h0 = __bfloat162float(__float2bfloat16_rn(v0));
        float h1 = __bfloat162float(__float2bfloat16_rn(v1));
        u32 off = (u32)(((kc * 4 + nt) * 32 + l) * 8 + word * 4);
        *(u32*)(smem + OFF_WHI + off) = packbf(v0, v1);
        *(u32*)(smem + OFF_WLO + off) = packbf(v0 - h0, v1 - h1);
    }
}

__device__ __forceinline__ void issue_chunk(u32 dst, const unsigned char* src, int tid) {
#pragma unroll
    for (int i = 0; i < 8; i++)
        asm volatile("cp.async.cg.shared.global [%0], [%1], 16;"
            :: "r"(dst + (u32)(tid * 16 + i * 4096)),
               "l"(src + (size_t)tid * 16 + (size_t)i * 4096) : "memory");
    asm volatile("cp.async.commit_group;" ::: "memory");
}

// Balanced, SMEM-staged K=1024 mainloop.
// A image [128 rows x 1024 k] split-bf16 (rows 0-63 hi, 64-127 lo).
// 12 m-slots (0-7: A x Whi, 8-11: A-top x Wlo) x 4 nt = 48 MMA jobs/kc,
// 6 per warp; warp w covers slots s0 = (6w)>>2 and s0+1.
__device__ void mma_mainloop2(const unsigned char* __restrict__ img, char* smem,
                              u32 smem_base, int tid) {
    const int wid = tid >> 5, lane = tid & 31;
    const int q0 = wid * 6;
    const int s0 = q0 >> 2;
    const int thr = (wid & 1) ? 2 : 4;   // jobs >= thr use slot s0+1
    const int mtA0 = (s0 < 8) ? s0 : s0 - 8;
    const int mtA1 = (s0 + 1 < 8) ? s0 + 1 : s0 - 7;

    float d[6][4];
#pragma unroll
    for (int j = 0; j < 6; j++)
#pragma unroll
        for (int p = 0; p < 4; p++) d[j][p] = 0.f;

    const u32 abufs[2] = { smem_base + OFF_A0, smem_base + OFF_A1 };
    issue_chunk(abufs[0], img, tid);
    issue_chunk(abufs[1], img + ABUF_B, tid);

    for (int c = 0; c < NCHK; c++) {
        if (c == NCHK - 1) asm volatile("cp.async.wait_group 0;" ::: "memory");
        else               asm volatile("cp.async.wait_group 1;" ::: "memory");
        __syncthreads();
        const u32 ab = abufs[c & 1];
#pragma unroll
        for (int kcl = 0; kcl < KCC; kcl++) {
            const int kc = c * KCC + kcl;
            uint4 aa[2];
            {
                u32 ad0 = ab + (u32)(((kcl * 8 + mtA0) * 32 + lane) * 16);
                u32 ad1 = ab + (u32)(((kcl * 8 + mtA1) * 32 + lane) * 16);
                asm volatile("ld.shared.v4.u32 {%0,%1,%2,%3}, [%4];"
                    : "=r"(aa[0].x), "=r"(aa[0].y), "=r"(aa[0].z), "=r"(aa[0].w) : "r"(ad0));
                asm volatile("ld.shared.v4.u32 {%0,%1,%2,%3}, [%4];"
                    : "=r"(aa[1].x), "=r"(aa[1].y), "=r"(aa[1].z), "=r"(aa[1].w) : "r"(ad1));
            }
#pragma unroll
            for (int j = 0; j < 6; j++) {
                int q = q0 + j;
                int s = q >> 2, nt = q & 3;
                int base = (s < 8) ? OFF_WHI : OFF_WLO;
                uint2 b = *(const uint2*)(smem + base + ((size_t)(kc * 4 + nt) * 32 + lane) * 8);
                mma_bf16(d[j], aa[(j >= thr) ? 1 : 0], b.x, b.y);
            }
        }
        __syncthreads();
        if (c + 2 < NCHK) issue_chunk(abufs[c & 1], img + (size_t)(c + 2) * ABUF_B, tid);
    }

    float* Zhi = (float*)(smem + OFF_ZHI);
    float* Zlo = (float*)(smem + OFF_ZLO);
    const int g = lane >> 2, tq = lane & 3;
#pragma unroll
    for (int j = 0; j < 6; j++) {
        int q = q0 + j;
        int s = q >> 2, nt = q & 3;
        int ccol = nt * 8 + tq * 2;
        if (s < 8) {
            Zhi[(s * 16 + g) * 33 + ccol]         = d[j][0];
            Zhi[(s * 16 + g) * 33 + ccol + 1]     = d[j][1];
            Zhi[(s * 16 + g + 8) * 33 + ccol]     = d[j][2];
            Zhi[(s * 16 + g + 8) * 33 + ccol + 1] = d[j][3];
        } else {
            Zlo[((s - 8) * 16 + g) * 33 + ccol]         = d[j][0];
            Zlo[((s - 8) * 16 + g) * 33 + ccol + 1]     = d[j][1];
            Zlo[((s - 8) * 16 + g + 8) * 33 + ccol]     = d[j][2];
            Zlo[((s - 8) * 16 + g + 8) * 33 + ccol + 1] = d[j][3];
        }
    }
}

// ---------------- SIMT GEMM helpers (layer-1 xg, K=64) ----------------
template <bool CG>
__device__ __forceinline__ void loadpair(ulonglong2 (&dst)[2], const float* p) {
    const ulonglong2* q = (const ulonglong2*)p;
    if (CG) { dst[0] = __ldcg(q); dst[1] = __ldcg(q + 1); }
    else    { dst[0] = __ldg(q);  dst[1] = __ldg(q + 1); }
}
__device__ __forceinline__ void compute_k(const float* __restrict__ Wp,
                                          const ulonglong2 (&hb)[2], ull (&acc)[8][4]) {
    float4 w0 = *(const float4*)Wp;
    float4 w1 = *(const float4*)(Wp + 4);
    ull h4[4] = {hb[0].x, hb[0].y, hb[1].x, hb[1].y};
    float wv[8] = {w0.x, w0.y, w0.z, w0.w, w1.x, w1.y, w1.z, w1.w};
#pragma unroll
    for (int j = 0; j < 8; j++) {
        ull ws = splat2(wv[j]);
#pragma unroll
        for (int p = 0; p < 4; p++) fma2(acc[j][p], ws, h4[p]);
    }
}
template <bool USE_CG>
__device__ __forceinline__ void accum_tile(const float* __restrict__ xin,
                                           const float* __restrict__ Ws,
                                           int k0, int kcnt, int colg, int batg,
                                           ull (&acc)[8][4]) {
    const float* base = xin + (size_t)k0 * B + batg * 8;
    const float* WsK = Ws + (size_t)k0 * 32 + colg * 8;
    ulonglong2 bufA[4][2], bufB[4][2];
#pragma unroll
    for (int i = 0; i < 4; i++) loadpair<USE_CG>(bufA[i], base + (size_t)i * B);
    int nPair = kcnt >> 3;
    for (int c = 0; c < nPair; c++) {
        int kb = c * 8;
#pragma unroll
        for (int i = 0; i < 4; i++)
            loadpair<USE_CG>(bufB[i], base + (size_t)(kb + 4 + i) * B);
#pragma unroll
        for (int i = 0; i < 4; i++)
            compute_k(WsK + (size_t)(kb + i) * 32, bufA[i], acc);
        int kq = (kb + 8 < kcnt) ? kb + 8 : 0;
#pragma unroll
        for (int i = 0; i < 4; i++)
            loadpair<USE_CG>(bufA[i], base + (size_t)(kq + i) * B);
#pragma unroll
        for (int i = 0; i < 4; i++)
            compute_k(WsK + (size_t)(kb + 4 + i) * 32, bufB[i], acc);
    }
}

__device__ void load_weights(const float* __restrict__ w, int K, float* Ws, int cb) {
    for (int j = 0; j < 32; j++) {
        int cg = ((j >> 3) * H) + cb * 8 + (j & 7);
        const float* src = w + (size_t)cg * K;
        for (int k = threadIdx.x; k < K; k += NTHR)
            Ws[(size_t)k * 32 + j] = src[k];
    }
}

// ---------------- kernel 1: transpose X[b][t][f] -> A[t][f][b] ----------------
__global__ void transpose_kernel(const float* __restrict__ X, float* __restrict__ A) {
    int idx = blockIdx.x * blockDim.x + threadIdx.x;
    if (idx >= T * F * B) return;
    int b = idx & (B - 1);
    int f = (idx >> 6) & (F - 1);
    int t = idx >> 12;
    A[idx] = X[((size_t)b * T + t) * F + f];
}

// ---------------- kernel 2a: layer-1 xg (SIMT fp32, K=64) ----------------
extern "C" __global__ void __launch_bounds__(NTHR, 1)
xg_kernel(const float* __restrict__ w_ih, const float* __restrict__ b_ih,
          const float* __restrict__ b_hh, const float* __restrict__ xin, int K) {
    extern __shared__ float smemf[];
    float* Ws = smemf;
    float* part = Ws + (size_t)K * 32;
    float* bias = part + 8 * 32 * PSTRIDE;
    int cb = blockIdx.x, tid = threadIdx.x;

    load_weights(w_ih, K, Ws, cb);
    if (tid < 32) {
        int cg = ((tid >> 3) * H) + cb * 8 + (tid & 7);
        bias[tid] = b_ih[cg] + b_hh[cg];
    }
    __syncthreads();

    int w = tid >> 5, lane = tid & 31;
    int colg = lane >> 3, batg = lane & 7;
    int kpw = K / 8, k0 = w * kpw;
    int colw = tid >> 3, b0w = (tid & 7) * 8;
    int cgw = ((colw >> 3) * H) + cb * 8 + (colw & 7);

    for (int t = 0; t < T; t++) {
        ull acc[8][4];
#pragma unroll
        for (int j = 0; j < 8; j++)
#pragma unroll
            for (int p = 0; p < 4; p++) acc[j][p] = 0ull;

        const float* xp = xin + (size_t)t * K * B;
        accum_tile<false>(xp, Ws, k0, kpw, colg, batg, acc);

        float* pw = part + (size_t)w * 32 * PSTRIDE;
#pragma unroll
        for (int j = 0; j < 8; j++) {
            int col = colg * 8 + j;
#pragma unroll
            for (int p = 0; p < 4; p++)
                *(ull*)(pw + (size_t)col * PSTRIDE + batg * 8 + p * 2) = acc[j][p];
        }
        __syncthreads();

        float s[8];
        float bsum = bias[colw];
#pragma unroll
        for (int i = 0; i < 8; i++) s[i] = bsum;
#pragma unroll
        for (int ww = 0; ww < 8; ww++) {
            const float* q = part + ((size_t)ww * 32 + colw) * PSTRIDE + b0w;
#pragma unroll
            for (int i = 0; i < 8; i++) s[i] += q[i];
        }
        float* dst = g_xg + ((size_t)t * G4H + cgw) * B + b0w;
        *(float4*)dst = make_float4(s[0], s[1], s[2], s[3]);
        *(float4*)(dst + 4) = make_float4(s[4], s[5], s[6], s[7]);
        __syncthreads();
    }
}

// ---------------- kernel 2b: convert act [T][K][B] -> split-bf16 frag image ----
__global__ void __launch_bounds__(256)
cvt_kernel(const float* __restrict__ act) {
    __shared__ float xs[64][65];
    int t = blockIdx.x, tid = threadIdx.x;
    unsigned char* out = &g_xImg[(size_t)t << 18];

    for (int kb = 0; kb < H; kb += 64) {
        __syncthreads();
        {
            int kl = tid >> 2, bq = (tid & 3) * 16;
            const float4* s = (const float4*)(act + ((size_t)t * H + kb + kl) * B + bq);
#pragma unroll
            for (int m = 0; m < 4; m++) {
                float4 v = s[m];
                xs[kl][bq + m * 4 + 0] = v.x; xs[kl][bq + m * 4 + 1] = v.y;
                xs[kl][bq + m * 4 + 2] = v.z; xs[kl][bq + m * 4 + 3] = v.w;
            }
        }
        __syncthreads();
        for (int e = tid; e < 1024; e += 256) {
            int l = e & 31, mt = (e >> 5) & 7, kcL = e >> 8;
            u32 wds[4];
#pragma unroll
            for (int w = 0; w < 4; w++) {
                int r = mt * 16 + (l >> 2) + (w & 1) * 8;
                int b = r & 63;
                int kl = kcL * 16 + (l & 3) * 2 + (w >> 1) * 8;
                float f0 = xs[kl][b], f1 = xs[kl + 1][b];
                if (r < 64) {
                    wds[w] = packbf(f0, f1);
                } else {
                    float h0 = __bfloat162float(__float2bfloat16_rn(f0));
                    float h1 = __bfloat162float(__float2bfloat16_rn(f1));
                    wds[w] = packbf(f0 - h0, f1 - h1);
                }
            }
            int kc = (kb >> 4) + kcL;
            *(uint4*)(out + ((size_t)((kc * 8 + mt) * 32 + l) << 4)) =
                make_uint4(wds[0], wds[1], wds[2], wds[3]);
        }
    }
}

// ---------------- kernel 2c: xg via HMMA (layers 2-3, K=1024) ----------------
extern "C" __global__ void __launch_bounds__(NTHR, 1)
xg_mma_kernel(const float* __restrict__ w_ih, const float* __restrict__ b_ih,
              const float* __restrict__ b_hh) {
    extern __shared__ char smem[];
    const u32 smem_base = smem_u32(smem);
    const int cb = blockIdx.x, tid = threadIdx.x;

    pack_w(w_ih, smem, cb, tid);
    float* bias = (float*)(smem + OFF_AUX);
    if (tid < 32) {
        int cg = ((tid >> 3) * H) + cb * 8 + (tid & 7);
        bias[tid] = b_ih[cg] + b_hh[cg];
    }
    __syncthreads();

    float* Zhi = (float*)(smem + OFF_ZHI);
    float* Zlo = (float*)(smem + OFF_ZLO);
    const int colw = tid >> 3, b0w = (tid & 7) * 8;
    const int cgw = ((colw >> 3) * H) + cb * 8 + (colw & 7);

    for (int t = 0; t < T; t++) {
        mma_mainloop2(&g_xImg[(size_t)t << 18], smem, smem_base, tid);
        __syncthreads();

        float bsum = bias[colw];
        float s[8];
#pragma unroll
        for (int i = 0; i < 8; i++) {
            int b = b0w + i;
            s[i] = Zhi[b * 33 + colw] + Zhi[(64 + b) * 33 + colw] + Zlo[b * 33 + colw] + bsum;
        }
        float* dst = g_xg + ((size_t)t * G4H + cgw) * B + b0w;
        *(float4*)dst = make_float4(s[0], s[1], s[2], s[3]);
        *(float4*)(dst + 4) = make_float4(s[4], s[5], s[6], s[7]);
        __syncthreads();
    }
}

// ---------------- kernel 3: recurrent scan — HMMA split-bf16, cp.async staged ----
extern "C" __global__ void __launch_bounds__(NTHR, 1)
rec_kernel(const float* __restrict__ w_hh, float* __restrict__ hseq) {
    extern __shared__ char smem[];
    const u32 smem_base = smem_u32(smem);
    const int cb = blockIdx.x, tid = threadIdx.x;
    const int wid = tid >> 5, lane = tid & 31;

    const unsigned base = *(volatile unsigned*)&g_flags2[cb];

    pack_w(w_hh, smem, cb, tid);
    __syncthreads();

    float* Zhi = (float*)(smem + OFF_ZHI);
    float* Zlo = (float*)(smem + OFF_ZLO);
    __nv_bfloat16* hsb = (__nv_bfloat16*)(smem + OFF_AUX);

    const int uglob = cb * 8 + wid;
    const int b0 = lane * 2;
    float c0 = 0.f, c1 = 0.f;

    for (int t = 0; t < T; t++) {
        float2 xgv[4];
#pragma unroll
        for (int g = 0; g < 4; g++)
            xgv[g] = __ldg((const float2*)(g_xg + ((size_t)t * G4H + g * H + uglob) * B + b0));

        if (t > 0)
            mma_mainloop2(&g_hImg[(t - 1) & 1][0], smem, smem_base, tid);
        __syncthreads();

        float z0[4], z1[4];
#pragma unroll
        for (int g = 0; g < 4; g++) {
            int j = g * 8 + wid;
            if (t > 0) {
                z0[g] = Zhi[b0 * 33 + j] + Zhi[(64 + b0) * 33 + j] + Zlo[b0 * 33 + j] + xgv[g].x;
                z1[g] = Zhi[(b0 + 1) * 33 + j] + Zhi[(64 + b0 + 1) * 33 + j] + Zlo[(b0 + 1) * 33 + j] + xgv[g].y;
            } else {
                z0[g] = xgv[g].x;
                z1[g] = xgv[g].y;
            }
        }
        float i0 = sigf(z0[0]), f0 = sigf(z0[1]), gg0 = tanhf(z0[2]), o0 = sigf(z0[3]);
        float i1 = sigf(z1[0]), f1 = sigf(z1[1]), gg1 = tanhf(z1[2]), o1 = sigf(z1[3]);
        c0 = f0 * c0 + i0 * gg0;
        c1 = f1 * c1 + i1 * gg1;
        float h0 = o0 * tanhf(c0);
        float h1 = o1 * tanhf(c1);

        *(float2*)(hseq + ((size_t)t * H + uglob) * B + b0) = make_float2(h0, h1);

        __nv_bfloat16 hh0 = __float2bfloat16_rn(h0);
        __nv_bfloat16 hh1 = __float2bfloat16_rn(h1);
        hsb[b0 * 8 + wid] = hh0;
        hsb[(b0 + 1) * 8 + wid] = hh1;
        hsb[(64 + b0) * 8 + wid] = __float2bfloat16_rn(h0 - __bfloat162float(hh0));
        hsb[(64 + b0 + 1) * 8 + wid] = __float2bfloat16_rn(h1 - __bfloat162float(hh1));
        __syncthreads();

        // publish fragment-packed image words (this CTA owns k = cb*8 .. cb*8+7)
        {
            unsigned char* imgW = &g_hImg[t & 1][0];
            int R = tid >> 1;
            int kbase = (tid & 1) * 2;
            int ri = R & 15, mt = R >> 4;
            int wbase = ((cb & 1) << 1) | (ri >> 3);
#pragma unroll
            for (int q = 0; q < 2; q++) {
                int kpl = kbase + q;
                u32 val = *(const u32*)((const char*)hsb + (R * 8 + 2 * kpl) * 2);
                int l = ((ri & 7) << 2) | kpl;
                size_t off = ((size_t)(((cb >> 1) * 8 + mt) * 32 + l) << 4) + (size_t)wbase * 4;
                *(u32*)(imgW + off) = val;
            }
        }
        grid_barrier2(base + (unsigned)t + 1u, tid, cb);
    }
}

// ---------------- kernel 4: projection ----------------
__global__ void __launch_bounds__(256)
proj_kernel(const float* __restrict__ hseq, const float* __restrict__ w_out,
            const float* __restrict__ b_out, float* __restrict__ out) {
    __shared__ float Sh[64][68];
    __shared__ float Sw[64][68];
    int t = blockIdx.x, tid = threadIdx.x;
    int fg = tid >> 4, bg = tid & 15;
    float accv[4][4];
#pragma unroll
    for (int i = 0; i < 4; i++)
#pragma unroll
        for (int j = 0; j < 4; j++) accv[i][j] = 0.f;

    for (int kc = 0; kc < H; kc += 64) {
        __syncthreads();
        {
            int i = tid >> 2, b = (tid & 3) * 16;
            const float4* src = (const float4*)(hseq + ((size_t)t * H + kc + i) * B + b);
#pragma unroll
            for (int m = 0; m < 4; m++) {
                float4 v = src[m];
                Sh[i][b + m * 4 + 0] = v.x; Sh[i][b + m * 4 + 1] = v.y;
                Sh[i][b + m * 4 + 2] = v.z; Sh[i][b + m * 4 + 3] = v.w;
            }
        }
        {
            int f = tid >> 2, kk = (tid & 3) * 16;
            const float4* src = (const float4*)(w_out + (size_t)f * H + kc + kk);
#pragma unroll
            for (int m = 0; m < 4; m++) {
                float4 v = src[m];
                Sw[kk + m * 4 + 0][f] = v.x; Sw[kk + m * 4 + 1][f] = v.y;
                Sw[kk + m * 4 + 2][f] = v.z; Sw[kk + m * 4 + 3][f] = v.w;
            }
        }
        __syncthreads();
#pragma unroll 4
        for (int k = 0; k < 64; k++) {
            float4 wv = *(const float4*)&Sw[k][fg * 4];
            float4 hv = *(const float4*)&Sh[k][bg * 4];
            float wr[4] = {wv.x, wv.y, wv.z, wv.w};
            float hr[4] = {hv.x, hv.y, hv.z, hv.w};
#pragma unroll
            for (int i = 0; i < 4; i++)
#pragma unroll
                for (int j = 0; j < 4; j++) accv[i][j] += wr[i] * hr[j];
        }
    }
    int fbase = fg * 4, bbase = bg * 4;
#pragma unroll
    for (int j = 0; j < 4; j++) {
        int b = bbase + j;
        float4 r;
        r.x = tanhf(accv[0][j] + b_out[fbase + 0]);
        r.y = tanhf(accv[1][j] + b_out[fbase + 1]);
        r.z = tanhf(accv[2][j] + b_out[fbase + 2]);
        r.w = tanhf(accv[3][j] + b_out[fbase + 3]);
        *(float4*)(out + ((size_t)b * T + t) * F + fbase) = r;
    }
}

// ---------------- launch ----------------
extern "C" void kernel_launch(void* const* d_in, const int* in_sizes, int n_in,
                              void* d_out, int out_size) {
    const float* X = (const float*)d_in[0];
    const float* w_ih[3] = {(const float*)d_in[1], (const float*)d_in[5], (const float*)d_in[9]};
    const float* w_hh[3] = {(const float*)d_in[2], (const float*)d_in[6], (const float*)d_in[10]};
    const float* b_ih[3] = {(const float*)d_in[3], (const float*)d_in[7], (const float*)d_in[11]};
    const float* b_hh[3] = {(const float*)d_in[4], (const float*)d_in[8], (const float*)d_in[12]};
    const float* w_out = (const float*)d_in[13];
    const float* b_out = (const float*)d_in[14];
    float* out = (float*)d_out;

    float *aA = nullptr, *aB = nullptr;
    cudaGetSymbolAddress((void**)&aA, g_actA);
    cudaGetSymbolAddress((void**)&aB, g_actB);

    const size_t smem_xg1 = ((size_t)F * 32 + 8 * 32 * PSTRIDE + 32) * sizeof(float);

    cudaFuncSetAttribute(xg_kernel, cudaFuncAttributeMaxDynamicSharedMemorySize, (int)smem_xg1);
    cudaFuncSetAttribute(rec_kernel, cudaFuncAttributeMaxDynamicSharedMemorySize, SMEM_REC);
    cudaFuncSetAttribute(xg_mma_kernel, cudaFuncAttributeMaxDynamicSharedMemorySize, SMEM_REC);

    transpose_kernel<<<(T * F * B + 255) / 256, 256>>>(X, aA);

    // layer 1
    xg_kernel<<<NCTA, NTHR, smem_xg1>>>(w_ih[0], b_ih[0], b_hh[0], aA, F);
    rec_kernel<<<NCTA, NTHR, SMEM_REC>>>(w_hh[0], aB);

    // layer 2
    cvt_kernel<<<T, 256>>>(aB);
    xg_mma_kernel<<<NCTA, NTHR, SMEM_REC>>>(w_ih[1], b_ih[1], b_hh[1]);
    rec_kernel<<<NCTA, NTHR, SMEM_REC>>>(w_hh[1], aA);

    // layer 3
    cvt_kernel<<<T, 256>>>(aA);
    xg_mma_kernel<<<NCTA, NTHR, SMEM_REC>>>(w_ih[2], b_ih[2], b_hh[2]);
    rec_kernel<<<NCTA, NTHR, SMEM_REC>>>(w_hh[2], aB);

    proj_kernel<<<T, 256>>>(aB, w_out, b_out, out);
}

// round 8
// speedup vs baseline: 3.3731x; 3.3731x over previous
#include <cuda_runtime.h>
#include <cuda_bf16.h>
#include <cuda_fp16.h>
#include <math.h>

#define B 64
#define T 256
#define F 64
#define H 1024
#define G4H 4096
#define NCTA 128
#define NTHR 256
#define PSTRIDE 66

typedef unsigned long long ull;
typedef unsigned int u32;

// ---------------- scratch globals ----------------
__device__ __align__(256) float g_xg[(size_t)T * G4H * B];   // [T][4096][B]
__device__ __align__(256) float g_actA[(size_t)T * H * B];   // [T][H][B]
__device__ __align__(256) float g_actB[(size_t)T * H * B];   // [T][H][B]
// fp16 fragment images, M=64: entry (kc, mt0..3, lane) -> 16B
__device__ __align__(256) unsigned char g_hImg[2][64 * 4 * 32 * 16];          // per-step h image (128KB each)
__device__ __align__(256) unsigned char g_xImg[(size_t)T * 64 * 4 * 32 * 16]; // per-t x image (32MB)
__device__ unsigned g_bar_count = 0;
__device__ unsigned g_bar_gen = 0;

// ---------------- generic helpers ----------------
__device__ __forceinline__ ull splat2(float x) {
    ull r; asm("mov.b64 %0, {%1, %1};" : "=l"(r) : "f"(x)); return r;
}
__device__ __forceinline__ void fma2(ull& d, ull a, ull b) {
    asm("fma.rn.f32x2 %0, %1, %2, %0;" : "+l"(d) : "l"(a), "l"(b));
}
__device__ __forceinline__ float sigf(float x) { return 1.f / (1.f + __expf(-x)); }

// proven grid barrier (R6)
__device__ __forceinline__ void grid_barrier() {
    __syncthreads();
    if (threadIdx.x == 0) {
        unsigned gen = *(volatile unsigned*)&g_bar_gen;
        __threadfence();
        unsigned arrived = atomicAdd(&g_bar_count, 1u);
        if (arrived == gridDim.x - 1u) {
            atomicExch(&g_bar_count, 0u);
            __threadfence();
            atomicAdd(&g_bar_gen, 1u);
        } else {
            while (*(volatile unsigned*)&g_bar_gen == gen) { }
        }
    }
    __syncthreads();
}

__device__ __forceinline__ u32 packhf(float a, float b) {
    __half2 h = __floats2half2_rn(a, b);   // .x = a (low half = first k)
    return *(u32*)&h;
}

// m16n8k16 fp16 inputs, fp32 accum (base ISA)
__device__ __forceinline__ void mma_f16(float* d, const uint4& a, u32 b0, u32 b1) {
    asm volatile(
        "mma.sync.aligned.m16n8k16.row.col.f32.f16.f16.f32 "
        "{%0,%1,%2,%3},{%4,%5,%6,%7},{%8,%9},{%0,%1,%2,%3};"
        : "+f"(d[0]), "+f"(d[1]), "+f"(d[2]), "+f"(d[3])
        : "r"(a.x), "r"(a.y), "r"(a.z), "r"(a.w), "r"(b0), "r"(b1));
}

__device__ __forceinline__ u32 ioff(int kc, int mt, int lane) {
    return (u32)(((kc * 4 + mt) * 32 + lane) << 4);
}
template <bool CG>
__device__ __forceinline__ uint4 ldimg(const unsigned char* img, int kc, int mt, int lane) {
    const uint4* p = (const uint4*)(img + ioff(kc, mt, lane));
    return CG ? __ldcg(p) : __ldg(p);
}

// ---------------- shared fp16 HMMA machinery ----------------
// SMEM layout (bytes):
#define OFF_W   0           // 64KB: [64 kc][4 nt][32 lane][2 u32] fp16 B-frags
#define OFF_Z   65536       // 64*33*4 = 8448
#define OFF_AUX 73984       // rec: hsb [64][8] fp16 (1KB); xg: bias[32] f32
#define SMEM_REC 75264

// Pack the CTA's 32 gate columns of W (K=H) into fp16 B-fragment layout.
__device__ void pack_w(const float* __restrict__ w, char* smem, int cb, int tid) {
    int nt = tid >> 6;            // 0..3
    int l  = (tid >> 1) & 31;
    int word = tid & 1;
    int j = nt * 8 + (l >> 2);    // local col 0..31
    int row = (j >> 3) * H + cb * 8 + (j & 7);
    const float* src = w + (size_t)row * H;
    for (int kc = 0; kc < 64; kc++) {
        int k0 = kc * 16 + (l & 3) * 2 + word * 8;
        u32 v = packhf(__ldg(src + k0), __ldg(src + k0 + 1));
        *(u32*)(smem + OFF_W + ((kc * 4 + nt) * 32 + l) * 8 + word * 4) = v;
    }
}

// fp16 K=1024 mainloop. A image: [64 batch rows x 1024 k] fp16, entries (kc, mt, lane).
// 16 jobs/kc (4 mt x 4 nt); warp w: mt = w>>1, nts = (w&1)*2 + {0,1}.
// 6-deep LDG ring hides L2 latency. Result -> Z[64][33] in SMEM.
template <bool CG>
__device__ void mma_mainloop(const unsigned char* __restrict__ img, char* smem,
                             int wid, int lane) {
    const int mt = wid >> 1;
    const int nt0 = (wid & 1) * 2;
    float d[2][4];
#pragma unroll
    for (int q = 0; q < 2; q++)
#pragma unroll
        for (int p = 0; p < 4; p++) d[q][p] = 0.f;

    uint4 rb[8];
#pragma unroll
    for (int p = 0; p < 6; p++) rb[p] = ldimg<CG>(img, p, mt, lane);

#pragma unroll 8
    for (int kc = 0; kc < 64; kc++) {
        uint4 a = rb[kc & 7];
        int pf = kc + 6;
        if (pf < 64) rb[pf & 7] = ldimg<CG>(img, pf, mt, lane);
#pragma unroll
        for (int q = 0; q < 2; q++) {
            uint2 b = *(const uint2*)(smem + OFF_W + ((size_t)(kc * 4 + nt0 + q) * 32 + lane) * 8);
            mma_f16(d[q], a, b.x, b.y);
        }
    }

    float* Z = (float*)(smem + OFF_Z);
    const int g = lane >> 2, tq = lane & 3;
#pragma unroll
    for (int q = 0; q < 2; q++) {
        int c = (nt0 + q) * 8 + tq * 2;
        Z[(mt * 16 + g) * 33 + c]         = d[q][0];
        Z[(mt * 16 + g) * 33 + c + 1]     = d[q][1];
        Z[(mt * 16 + g + 8) * 33 + c]     = d[q][2];
        Z[(mt * 16 + g + 8) * 33 + c + 1] = d[q][3];
    }
}

// ---------------- SIMT GEMM helpers (layer-1 xg, K=64) ----------------
template <bool CG>
__device__ __forceinline__ void loadpair(ulonglong2 (&dst)[2], const float* p) {
    const ulonglong2* q = (const ulonglong2*)p;
    if (CG) { dst[0] = __ldcg(q); dst[1] = __ldcg(q + 1); }
    else    { dst[0] = __ldg(q);  dst[1] = __ldg(q + 1); }
}
__device__ __forceinline__ void compute_k(const float* __restrict__ Wp,
                                          const ulonglong2 (&hb)[2], ull (&acc)[8][4]) {
    float4 w0 = *(const float4*)Wp;
    float4 w1 = *(const float4*)(Wp + 4);
    ull h4[4] = {hb[0].x, hb[0].y, hb[1].x, hb[1].y};
    float wv[8] = {w0.x, w0.y, w0.z, w0.w, w1.x, w1.y, w1.z, w1.w};
#pragma unroll
    for (int j = 0; j < 8; j++) {
        ull ws = splat2(wv[j]);
#pragma unroll
        for (int p = 0; p < 4; p++) fma2(acc[j][p], ws, h4[p]);
    }
}
template <bool USE_CG>
__device__ __forceinline__ void accum_tile(const float* __restrict__ xin,
                                           const float* __restrict__ Ws,
                                           int k0, int kcnt, int colg, int batg,
                                           ull (&acc)[8][4]) {
    const float* base = xin + (size_t)k0 * B + batg * 8;
    const float* WsK = Ws + (size_t)k0 * 32 + colg * 8;
    ulonglong2 bufA[4][2], bufB[4][2];
#pragma unroll
    for (int i = 0; i < 4; i++) loadpair<USE_CG>(bufA[i], base + (size_t)i * B);
    int nPair = kcnt >> 3;
    for (int c = 0; c < nPair; c++) {
        int kb = c * 8;
#pragma unroll
        for (int i = 0; i < 4; i++)
            loadpair<USE_CG>(bufB[i], base + (size_t)(kb + 4 + i) * B);
#pragma unroll
        for (int i = 0; i < 4; i++)
            compute_k(WsK + (size_t)(kb + i) * 32, bufA[i], acc);
        int kq = (kb + 8 < kcnt) ? kb + 8 : 0;
#pragma unroll
        for (int i = 0; i < 4; i++)
            loadpair<USE_CG>(bufA[i], base + (size_t)(kq + i) * B);
#pragma unroll
        for (int i = 0; i < 4; i++)
            compute_k(WsK + (size_t)(kb + 4 + i) * 32, bufB[i], acc);
    }
}

__device__ void load_weights(const float* __restrict__ w, int K, float* Ws, int cb) {
    for (int j = 0; j < 32; j++) {
        int cg = ((j >> 3) * H) + cb * 8 + (j & 7);
        const float* src = w + (size_t)cg * K;
        for (int k = threadIdx.x; k < K; k += NTHR)
            Ws[(size_t)k * 32 + j] = src[k];
    }
}

// ---------------- kernel 1: transpose X[b][t][f] -> A[t][f][b] ----------------
__global__ void transpose_kernel(const float* __restrict__ X, float* __restrict__ A) {
    int idx = blockIdx.x * blockDim.x + threadIdx.x;
    if (idx >= T * F * B) return;
    int b = idx & (B - 1);
    int f = (idx >> 6) & (F - 1);
    int t = idx >> 12;
    A[idx] = X[((size_t)b * T + t) * F + f];
}

// ---------------- kernel 2a: layer-1 xg (SIMT fp32, K=64) ----------------
extern "C" __global__ void __launch_bounds__(NTHR, 1)
xg_kernel(const float* __restrict__ w_ih, const float* __restrict__ b_ih,
          const float* __restrict__ b_hh, const float* __restrict__ xin, int K) {
    extern __shared__ float smemf[];
    float* Ws = smemf;
    float* part = Ws + (size_t)K * 32;
    float* bias = part + 8 * 32 * PSTRIDE;
    int cb = blockIdx.x, tid = threadIdx.x;

    load_weights(w_ih, K, Ws, cb);
    if (tid < 32) {
        int cg = ((tid >> 3) * H) + cb * 8 + (tid & 7);
        bias[tid] = b_ih[cg] + b_hh[cg];
    }
    __syncthreads();

    int w = tid >> 5, lane = tid & 31;
    int colg = lane >> 3, batg = lane & 7;
    int kpw = K / 8, k0 = w * kpw;
    int colw = tid >> 3, b0w = (tid & 7) * 8;
    int cgw = ((colw >> 3) * H) + cb * 8 + (colw & 7);

    for (int t = 0; t < T; t++) {
        ull acc[8][4];
#pragma unroll
        for (int j = 0; j < 8; j++)
#pragma unroll
            for (int p = 0; p < 4; p++) acc[j][p] = 0ull;

        const float* xp = xin + (size_t)t * K * B;
        accum_tile<false>(xp, Ws, k0, kpw, colg, batg, acc);

        float* pw = part + (size_t)w * 32 * PSTRIDE;
#pragma unroll
        for (int j = 0; j < 8; j++) {
            int col = colg * 8 + j;
#pragma unroll
            for (int p = 0; p < 4; p++)
                *(ull*)(pw + (size_t)col * PSTRIDE + batg * 8 + p * 2) = acc[j][p];
        }
        __syncthreads();

        float s[8];
        float bsum = bias[colw];
#pragma unroll
        for (int i = 0; i < 8; i++) s[i] = bsum;
#pragma unroll
        for (int ww = 0; ww < 8; ww++) {
            const float* q = part + ((size_t)ww * 32 + colw) * PSTRIDE + b0w;
#pragma unroll
            for (int i = 0; i < 8; i++) s[i] += q[i];
        }
        float* dst = g_xg + ((size_t)t * G4H + cgw) * B + b0w;
        *(float4*)dst = make_float4(s[0], s[1], s[2], s[3]);
        *(float4*)(dst + 4) = make_float4(s[4], s[5], s[6], s[7]);
        __syncthreads();
    }
}

// ---------------- kernel 2b: convert act [T][K][B] -> fp16 frag image ----------
__global__ void __launch_bounds__(256)
cvt_kernel(const float* __restrict__ act) {
    __shared__ float xs[64][65];
    int t = blockIdx.x, tid = threadIdx.x;
    unsigned char* out = &g_xImg[(size_t)t << 17];

    for (int kb = 0; kb < H; kb += 64) {
        __syncthreads();
        {   // stage xs[kl][b] = act[t][kb+kl][b]  (coalesced)
            int kl = tid >> 2, bq = (tid & 3) * 16;
            const float4* s = (const float4*)(act + ((size_t)t * H + kb + kl) * B + bq);
#pragma unroll
            for (int m = 0; m < 4; m++) {
                float4 v = s[m];
                xs[kl][bq + m * 4 + 0] = v.x; xs[kl][bq + m * 4 + 1] = v.y;
                xs[kl][bq + m * 4 + 2] = v.z; xs[kl][bq + m * 4 + 3] = v.w;
            }
        }
        __syncthreads();
        // emit 512 fragment entries (4 kcL x 4 mt x 32 lane), uint4 each
        for (int e = tid; e < 512; e += 256) {
            int lane = e & 31, mt = (e >> 5) & 3, kcL = e >> 7;
            int k0 = kcL * 16 + (lane & 3) * 2;
            int r = mt * 16 + (lane >> 2);
            uint4 v;
            v.x = packhf(xs[k0][r],     xs[k0 + 1][r]);
            v.y = packhf(xs[k0][r + 8], xs[k0 + 1][r + 8]);
            v.z = packhf(xs[k0 + 8][r],     xs[k0 + 9][r]);
            v.w = packhf(xs[k0 + 8][r + 8], xs[k0 + 9][r + 8]);
            int kc = (kb >> 4) + kcL;
            *(uint4*)(out + ioff(kc, mt, lane)) = v;
        }
    }
}

// ---------------- kernel 2c: xg via fp16 HMMA (layers 2-3) ----------------
extern "C" __global__ void __launch_bounds__(NTHR, 1)
xg_mma_kernel(const float* __restrict__ w_ih, const float* __restrict__ b_ih,
              const float* __restrict__ b_hh) {
    extern __shared__ char smem[];
    const int cb = blockIdx.x, tid = threadIdx.x;
    const int wid = tid >> 5, lane = tid & 31;

    pack_w(w_ih, smem, cb, tid);
    float* bias = (float*)(smem + OFF_AUX);
    if (tid < 32) {
        int cg = ((tid >> 3) * H) + cb * 8 + (tid & 7);
        bias[tid] = b_ih[cg] + b_hh[cg];
    }
    __syncthreads();

    float* Z = (float*)(smem + OFF_Z);
    const int colw = tid >> 3, b0w = (tid & 7) * 8;
    const int cgw = ((colw >> 3) * H) + cb * 8 + (colw & 7);

    for (int t = 0; t < T; t++) {
        mma_mainloop<false>(&g_xImg[(size_t)t << 17], smem, wid, lane);
        __syncthreads();

        float bsum = bias[colw];
        float s[8];
#pragma unroll
        for (int i = 0; i < 8; i++)
            s[i] = Z[(b0w + i) * 33 + colw] + bsum;
        float* dst = g_xg + ((size_t)t * G4H + cgw) * B + b0w;
        *(float4*)dst = make_float4(s[0], s[1], s[2], s[3]);
        *(float4*)(dst + 4) = make_float4(s[4], s[5], s[6], s[7]);
        __syncthreads();
    }
}

// ---------------- kernel 3: recurrent scan — fp16 HMMA ----------------
extern "C" __global__ void __launch_bounds__(NTHR, 1)
rec_kernel(const float* __restrict__ w_hh, float* __restrict__ hseq) {
    extern __shared__ char smem[];
    const int cb = blockIdx.x, tid = threadIdx.x;
    const int wid = tid >> 5, lane = tid & 31;

    pack_w(w_hh, smem, cb, tid);
    __syncthreads();

    float* Z = (float*)(smem + OFF_Z);
    __half* hsb = (__half*)(smem + OFF_AUX);     // [64 batch][8 unit]

    const int uglob = cb * 8 + wid;
    const int b0 = lane * 2;
    float c0 = 0.f, c1 = 0.f;

    for (int t = 0; t < T; t++) {
        float2 xgv[4];
#pragma unroll
        for (int g = 0; g < 4; g++)
            xgv[g] = __ldg((const float2*)(g_xg + ((size_t)t * G4H + g * H + uglob) * B + b0));

        if (t > 0)
            mma_mainloop<true>(&g_hImg[(t - 1) & 1][0], smem, wid, lane);
        __syncthreads();

        float z0[4], z1[4];
#pragma unroll
        for (int g = 0; g < 4; g++) {
            int j = g * 8 + wid;
            if (t > 0) {
                z0[g] = Z[b0 * 33 + j] + xgv[g].x;
                z1[g] = Z[(b0 + 1) * 33 + j] + xgv[g].y;
            } else {
                z0[g] = xgv[g].x;
                z1[g] = xgv[g].y;
            }
        }
        float i0 = sigf(z0[0]), f0 = sigf(z0[1]), gg0 = tanhf(z0[2]), o0 = sigf(z0[3]);
        float i1 = sigf(z1[0]), f1 = sigf(z1[1]), gg1 = tanhf(z1[2]), o1 = sigf(z1[3]);
        c0 = f0 * c0 + i0 * gg0;
        c1 = f1 * c1 + i1 * gg1;
        float h0 = o0 * tanhf(c0);
        float h1 = o1 * tanhf(c1);

        *(float2*)(hseq + ((size_t)t * H + uglob) * B + b0) = make_float2(h0, h1);

        hsb[b0 * 8 + wid] = __float2half_rn(h0);
        hsb[(b0 + 1) * 8 + wid] = __float2half_rn(h1);
        __syncthreads();

        // publish fp16 image words: this CTA owns k = cb*8 .. cb*8+7
        {
            int r = tid >> 2, kp = tid & 3;
            u32 val = ((const u32*)hsb)[r * 4 + kp];
            u32 off = ioff(cb >> 1, r >> 4, (r & 7) * 4 + kp) +
                      (u32)(((cb & 1) * 2 + ((r >> 3) & 1)) * 4);
            *(u32*)(&g_hImg[t & 1][0] + off) = val;
        }
        __threadfence();
        grid_barrier();
    }
}

// ---------------- kernel 4: projection ----------------
__global__ void __launch_bounds__(256)
proj_kernel(const float* __restrict__ hseq, const float* __restrict__ w_out,
            const float* __restrict__ b_out, float* __restrict__ out) {
    __shared__ float Sh[64][68];
    __shared__ float Sw[64][68];
    int t = blockIdx.x, tid = threadIdx.x;
    int fg = tid >> 4, bg = tid & 15;
    float accv[4][4];
#pragma unroll
    for (int i = 0; i < 4; i++)
#pragma unroll
        for (int j = 0; j < 4; j++) accv[i][j] = 0.f;

    for (int kc = 0; kc < H; kc += 64) {
        __syncthreads();
        {
            int i = tid >> 2, b = (tid & 3) * 16;
            const float4* src = (const float4*)(hseq + ((size_t)t * H + kc + i) * B + b);
#pragma unroll
            for (int m = 0; m < 4; m++) {
                float4 v = src[m];
                Sh[i][b + m * 4 + 0] = v.x; Sh[i][b + m * 4 + 1] = v.y;
                Sh[i][b + m * 4 + 2] = v.z; Sh[i][b + m * 4 + 3] = v.w;
            }
        }
        {
            int f = tid >> 2, kk = (tid & 3) * 16;
            const float4* src = (const float4*)(w_out + (size_t)f * H + kc + kk);
#pragma unroll
            for (int m = 0; m < 4; m++) {
                float4 v = src[m];
                Sw[kk + m * 4 + 0][f] = v.x; Sw[kk + m * 4 + 1][f] = v.y;
                Sw[kk + m * 4 + 2][f] = v.z; Sw[kk + m * 4 + 3][f] = v.w;
            }
        }
        __syncthreads();
#pragma unroll 4
        for (int k = 0; k < 64; k++) {
            float4 wv = *(const float4*)&Sw[k][fg * 4];
            float4 hv = *(const float4*)&Sh[k][bg * 4];
            float wr[4] = {wv.x, wv.y, wv.z, wv.w};
            float hr[4] = {hv.x, hv.y, hv.z, hv.w};
#pragma unroll
            for (int i = 0; i < 4; i++)
#pragma unroll
                for (int j = 0; j < 4; j++) accv[i][j] += wr[i] * hr[j];
        }
    }
    int fbase = fg * 4, bbase = bg * 4;
#pragma unroll
    for (int j = 0; j < 4; j++) {
        int b = bbase + j;
        float4 r;
        r.x = tanhf(accv[0][j] + b_out[fbase + 0]);
        r.y = tanhf(accv[1][j] + b_out[fbase + 1]);
        r.z = tanhf(accv[2][j] + b_out[fbase + 2]);
        r.w = tanhf(accv[3][j] + b_out[fbase + 3]);
        *(float4*)(out + ((size_t)b * T + t) * F + fbase) = r;
    }
}

// ---------------- launch ----------------
extern "C" void kernel_launch(void* const* d_in, const int* in_sizes, int n_in,
                              void* d_out, int out_size) {
    const float* X = (const float*)d_in[0];
    const float* w_ih[3] = {(const float*)d_in[1], (const float*)d_in[5], (const float*)d_in[9]};
    const float* w_hh[3] = {(const float*)d_in[2], (const float*)d_in[6], (const float*)d_in[10]};
    const float* b_ih[3] = {(const float*)d_in[3], (const float*)d_in[7], (const float*)d_in[11]};
    const float* b_hh[3] = {(const float*)d_in[4], (const float*)d_in[8], (const float*)d_in[12]};
    const float* w_out = (const float*)d_in[13];
    const float* b_out = (const float*)d_in[14];
    float* out = (float*)d_out;

    float *aA = nullptr, *aB = nullptr;
    cudaGetSymbolAddress((void**)&aA, g_actA);
    cudaGetSymbolAddress((void**)&aB, g_actB);

    const size_t smem_xg1 = ((size_t)F * 32 + 8 * 32 * PSTRIDE + 32) * sizeof(float);

    cudaFuncSetAttribute(xg_kernel, cudaFuncAttributeMaxDynamicSharedMemorySize, (int)smem_xg1);
    cudaFuncSetAttribute(rec_kernel, cudaFuncAttributeMaxDynamicSharedMemorySize, SMEM_REC);
    cudaFuncSetAttribute(xg_mma_kernel, cudaFuncAttributeMaxDynamicSharedMemorySize, SMEM_REC);

    transpose_kernel<<<(T * F * B + 255) / 256, 256>>>(X, aA);

    // layer 1
    xg_kernel<<<NCTA, NTHR, smem_xg1>>>(w_ih[0], b_ih[0], b_hh[0], aA, F);
    rec_kernel<<<NCTA, NTHR, SMEM_REC>>>(w_hh[0], aB);

    // layer 2
    cvt_kernel<<<T, 256>>>(aB);
    xg_mma_kernel<<<NCTA, NTHR, SMEM_REC>>>(w_ih[1], b_ih[1], b_hh[1]);
    rec_kernel<<<NCTA, NTHR, SMEM_REC>>>(w_hh[1], aA);

    // layer 3
    cvt_kernel<<<T, 256>>>(aA);
    xg_mma_kernel<<<NCTA, NTHR, SMEM_REC>>>(w_ih[2], b_ih[2], b_hh[2]);
    rec_kernel<<<NCTA, NTHR, SMEM_REC>>>(w_hh[2], aB);

    proj_kernel<<<T, 256>>>(aB, w_out, b_out, out);
}